// round 7
// baseline (speedup 1.0000x reference)
#include <cuda_runtime.h>
#include <cuda_fp16.h>
#include <cuda_bf16.h>

// FFT-based 2x upsample, fully-real polyphase formulation (see R2/R3/R5).
// R7: structural register reduction in the FFT kernels (twiddles staged in
// smem + volatile re-reads; K1 reloads originals from L2-resident x) so that
// 2 CTAs/SM fit WITHOUT spills; K4 uses 64-wide tiles + float4 stores.

#define FN    4096
#define TPB   512
#define NPAIR (FN / 2)
// dyn smem: buf0[4096] buf1[4096] w1s[512] w2s[512] w3s[512] wms[512] float2
#define SMEM_FFT ((2 * FN + 4 * 512) * sizeof(float2))   // 81920 B

__device__ __align__(16) __half2 g_B [(size_t)FN * FN];  // (x, R_row)
__device__ __align__(16) __half2 g_Bt[(size_t)FN * FN];  // B transposed
__device__ __align__(16) __half2 g_R [(size_t)FN * FN];  // (Ru, Rv') per (c,i)
__device__ float g_Dpart[NPAIR];
__device__ float g_D[1];
// twA[k] = e^{-2 pi i k/4096}, twB[k] = e^{+i pi k/4096}, k < 512
__device__ __align__(16) float2 g_twA[512];
__device__ __align__(16) float2 g_twB[512];

__device__ __forceinline__ float2 cmul(float2 a, float2 b) {
    return make_float2(fmaf(a.x, b.x, -a.y * b.y), fmaf(a.x, b.y, a.y * b.x));
}
__device__ __forceinline__ float2 cadd(float2 a, float2 b) { return make_float2(a.x + b.x, a.y + b.y); }
__device__ __forceinline__ float2 csub(float2 a, float2 b) { return make_float2(a.x - b.x, a.y - b.y); }
__device__ __forceinline__ float2 cconj(float2 a) { return make_float2(a.x, -a.y); }

// volatile smem read (uncacheable -> live range starts HERE, not hoistable)
__device__ __forceinline__ float2 vld(const volatile float2* p, int i) {
    return make_float2(p[i].x, p[i].y);
}

// Bank swizzle (see R3): bijective on [0,4096), conflict-free for all six
// exchange patterns.
__device__ __forceinline__ int SW(int a) {
    return a ^ ((a >> 2) & 4) ^ ((a >> 4) & 2) ^ (((a >> 6) & 1) * 9);
}

__global__ void k0_twiddle() {
    int k = threadIdx.x;
    float sn, cs;
    sincospif(-(float)k / 2048.0f, &sn, &cs);
    g_twA[k] = make_float2(cs, sn);
    sincospif((float)k / 4096.0f, &sn, &cs);
    g_twB[k] = make_float2(cs, sn);
}

// Radix-8 DFT butterfly. FWD: W_8 = e^{-2pi i/8}; INV: conjugate.
template <bool INV>
__device__ __forceinline__ void bfly8(const float2 x[8], float2 y[8]) {
    float2 a0 = cadd(x[0], x[4]), a1 = csub(x[0], x[4]);
    float2 a2 = cadd(x[2], x[6]), a3 = csub(x[2], x[6]);
    float2 a4 = cadd(x[1], x[5]), a5 = csub(x[1], x[5]);
    float2 a6 = cadd(x[3], x[7]), a7 = csub(x[3], x[7]);
    float2 b0 = cadd(a0, a2), b1 = csub(a0, a2);
    float2 b2 = cadd(a4, a6), b3 = csub(a4, a6);
    float2 c3  = INV ? make_float2(-a3.y, a3.x) : make_float2(a3.y, -a3.x);
    float2 c7  = INV ? make_float2(-a7.y, a7.x) : make_float2(a7.y, -a7.x);
    float2 jb3 = INV ? make_float2(-b3.y, b3.x) : make_float2(b3.y, -b3.x);
    float2 e1 = cadd(a1, c3), e3 = csub(a1, c3);
    float2 f5 = cadd(a5, c7), f7 = csub(a5, c7);
    const float s = 0.70710678118654752440f;
    float2 W1 = INV ? make_float2(s, s)  : make_float2(s, -s);
    float2 W3 = INV ? make_float2(-s, s) : make_float2(-s, -s);
    float2 g5 = cmul(W1, f5), g7 = cmul(W3, f7);
    y[0] = cadd(b0, b2); y[4] = csub(b0, b2);
    y[2] = cadd(b1, jb3); y[6] = csub(b1, jb3);
    y[1] = cadd(e1, g5); y[5] = csub(e1, g5);
    y[3] = cadd(e3, g7); y[7] = csub(e3, g7);
}

__device__ __forceinline__ void twapply(float2 y[8], float2 w) {
    float2 wk = w;
    y[1] = cmul(y[1], wk);
    #pragma unroll
    for (int k = 2; k < 8; k++) { wk = cmul(wk, w); y[k] = cmul(y[k], wk); }
}

// S-transform: z <- N * IDFT( DFT(z) * halfshift_w ), zny <- DFT(z)[2048].
// Twiddle bases are staged per-tid in smem and re-read (volatile) per stage.
__device__ __forceinline__ void stransform(float2 z[8], float2* dsm,
                                           float2* s_zny, int tid, float2* zny_out) {
    float2* buf0 = dsm;
    float2* buf1 = dsm + FN;
    volatile float2* w1s = dsm + 2 * FN;
    volatile float2* w2s = dsm + 2 * FN + 512;
    volatile float2* w3s = dsm + 2 * FN + 1024;
    volatile float2* wms = dsm + 2 * FN + 1536;

    const int k0 = tid >> 6;
    const int s6 = tid & 63;
    const int k1 = (tid >> 3) & 7;
    const int n0 = tid & 7;
    float2 y[8], t[8];

    // stage twiddles (each thread reads only its OWN slot later; no sync needed)
    {
        float2 a = __ldg(&g_twA[tid]);
        float2 b = __ldg(&g_twA[8 * s6]);
        float2 c = __ldg(&g_twA[64 * n0]);
        float2 d = __ldg(&g_twB[k0 + 8 * k1 + 64 * n0]);
        w1s[tid].x = a.x; w1s[tid].y = a.y;
        w2s[tid].x = b.x; w2s[tid].y = b.y;
        w3s[tid].x = c.x; w3s[tid].y = c.y;
        wms[tid].x = d.x; wms[tid].y = d.y;
    }

    // ---- forward FFT ----
    bfly8<false>(z, y);
    twapply(y, vld(w1s, tid));
    #pragma unroll
    for (int q = 0; q < 8; q++) buf0[SW(512 * q + tid)] = y[q];
    __syncthreads();
    #pragma unroll
    for (int q = 0; q < 8; q++) t[q] = buf0[SW(512 * k0 + 64 * q + s6)];

    bfly8<false>(t, y);
    twapply(y, vld(w2s, tid));
    #pragma unroll
    for (int q = 0; q < 8; q++) buf1[SW(512 * k0 + 64 * q + s6)] = y[q];
    __syncthreads();
    #pragma unroll
    for (int q = 0; q < 8; q++) t[q] = buf1[SW(512 * k0 + 64 * k1 + 8 * q + n0)];

    bfly8<false>(t, y);
    twapply(y, vld(w3s, tid));
    #pragma unroll
    for (int q = 0; q < 8; q++) buf0[SW(512 * k0 + 64 * k1 + 8 * q + n0)] = y[q];
    __syncthreads();
    #pragma unroll
    for (int q = 0; q < 8; q++) t[q] = buf0[SW(8 * tid + q)];

    bfly8<false>(t, y);                         // -> X[m + 512 j]
    if (tid == 0) *s_zny = y[4];                // zny = X[2048]

    // ---- half-sample-shift phase (registers) ----
    {
        float2 wm = vld(wms, tid);
        const float2 EJ[8] = {
            { 1.0f, 0.0f},
            { 0.92387953251128675613f,  0.38268343236508977173f},
            { 0.70710678118654752440f,  0.70710678118654752440f},
            { 0.38268343236508977173f,  0.92387953251128675613f},
            { 0.0f, -1.0f},
            { 0.38268343236508977173f, -0.92387953251128675613f},
            { 0.70710678118654752440f, -0.70710678118654752440f},
            { 0.92387953251128675613f, -0.38268343236508977173f}};
        #pragma unroll
        for (int j = 0; j < 8; j++) y[j] = cmul(y[j], cmul(wm, EJ[j]));
    }

    // ---- inverse FFT ----
    bfly8<true>(y, t);
    #pragma unroll
    for (int q = 0; q < 8; q++) buf1[SW(8 * tid + q)] = t[q];
    __syncthreads();
    #pragma unroll
    for (int q = 0; q < 8; q++) t[q] = buf1[SW(512 * k0 + 64 * k1 + 8 * q + n0)];

    twapply(t, cconj(vld(w3s, tid)));
    bfly8<true>(t, y);
    #pragma unroll
    for (int q = 0; q < 8; q++) buf0[SW(512 * k0 + 64 * k1 + 8 * q + n0)] = y[q];
    __syncthreads();
    #pragma unroll
    for (int q = 0; q < 8; q++) t[q] = buf0[SW(512 * k0 + 64 * q + s6)];

    twapply(t, cconj(vld(w2s, tid)));
    bfly8<true>(t, y);
    #pragma unroll
    for (int q = 0; q < 8; q++) buf1[SW(512 * k0 + 64 * q + s6)] = y[q];
    __syncthreads();
    #pragma unroll
    for (int q = 0; q < 8; q++) t[q] = buf1[SW(512 * q + tid)];

    twapply(t, cconj(vld(w1s, tid)));
    bfly8<true>(t, z);                          // z[n3] = N*S[tid+512 n3]

    *zny_out = *s_zny;                          // >= 3 syncs after the write
}

// K1: 2-for-1 row pass (block r handles input rows 2r, 2r+1).
// Originals are RE-LOADED from x (L2-resident) after the transform: no z0 regs.
__global__ __launch_bounds__(TPB, 2) void k1_rowpass(const float* __restrict__ x) {
    extern __shared__ float2 dsm[];
    __shared__ float2 s_zny;
    int tid = threadIdx.x;
    size_t r = blockIdx.x;
    const float* u = x + (2 * r) * (size_t)FN;
    const float* v = u + FN;
    float2 z[8];
    #pragma unroll
    for (int e = 0; e < 8; e++) {
        int j = tid + e * TPB;
        z[e] = make_float2(u[j], v[j]);
    }
    float2 zny;
    stransform(z, dsm, &s_zny, tid, &zny);
    if (tid == 0) g_Dpart[r] = zny.x - zny.y;

    const float invN = 1.0f / 4096.0f;
    float sgn = (tid & 1) ? -1.0f : 1.0f;       // (-1)^j
    __half2* row0 = g_B + (2 * r) * (size_t)FN;
    __half2* row1 = row0 + FN;
    const volatile float* uv = u;               // volatile: not CSE'd with first load
    const volatile float* vv = v;
    #pragma unroll
    for (int e = 0; e < 8; e++) {
        int j = tid + e * TPB;
        float Ru = (z[e].x - sgn * zny.y) * invN;
        float Rv = (z[e].y + sgn * zny.x) * invN;
        row0[j] = __floats2half2_rn(uv[j], Ru);
        row1[j] = __floats2half2_rn(vv[j], Rv);
    }
}

// Deterministic reduction of g_Dpart -> g_D.
__global__ void k_reduce() {
    __shared__ float sh[TPB];
    float s = 0.0f;
    for (int i = threadIdx.x; i < NPAIR; i += TPB) s += g_Dpart[i];
    sh[threadIdx.x] = s;
    __syncthreads();
    for (int o = TPB / 2; o > 0; o >>= 1) {
        if (threadIdx.x < o) sh[threadIdx.x] += sh[threadIdx.x + o];
        __syncthreads();
    }
    if (threadIdx.x == 0) g_D[0] = sh[0];
}

// K2: transpose B [4096x4096 half2] -> Bt.
__global__ void k2_transpose() {
    __shared__ __half2 tile[32][33];
    int tx = threadIdx.x, ty = threadIdx.y;
    int cx = blockIdx.x * 32 + tx;
    int ry = blockIdx.y * 32 + ty;
    #pragma unroll
    for (int j = 0; j < 32; j += 8)
        tile[ty + j][tx] = g_B[(size_t)(ry + j) * FN + cx];
    __syncthreads();
    int ox = blockIdx.y * 32 + tx;
    int oy = blockIdx.x * 32 + ty;
    #pragma unroll
    for (int j = 0; j < 32; j += 8)
        g_Bt[(size_t)(oy + j) * FN + ox] = tile[tx][ty + j];
}

// K3: 2-for-1 column pass (block c handles output columns 2c, 2c+1).
__global__ __launch_bounds__(TPB, 2) void k3_colpass() {
    extern __shared__ float2 dsm[];
    __shared__ float2 s_zny;
    int tid = threadIdx.x;
    size_t c = blockIdx.x;
    const __half2* bt = g_Bt + c * (size_t)FN;
    float2 z[8];
    #pragma unroll
    for (int e = 0; e < 8; e++) {
        int j = tid + e * TPB;
        z[e] = __half22float2(bt[j]);
    }
    float2 zny;
    stransform(z, dsm, &s_zny, tid, &zny);

    const float invN = 1.0f / 4096.0f;
    float corr = -g_D[0] * invN * invN;         // -D/N^2
    float sgnc = (c & 1) ? -corr : corr;        // (-1)^c * corr
    float sgn = (tid & 1) ? -1.0f : 1.0f;       // (-1)^i
    __half2* rr = g_R + c * (size_t)FN;
    #pragma unroll
    for (int e = 0; e < 8; e++) {
        int j = tid + e * TPB;
        float Ru = (z[e].x - sgn * zny.y) * invN;
        float Rv = (z[e].y + sgn * zny.x) * invN;
        rr[j] = __floats2half2_rn(Ru, Rv + sgn * sgnc);
    }
}

// K4: assemble output from Bt + R; 64-wide c tiles, float4 stores.
//   out[2i  ][2c..2c+1] = Bt[c][i]   out[2i+1][2c..2c+1] = R[c][i]
__global__ void k4_assemble(float* __restrict__ out) {
    __shared__ __half2 tB[32][66];   // [i_loc][c_loc], +2 pad
    __shared__ __half2 tR[32][66];
    int tx = threadIdx.x, ty = threadIdx.y;    // 32 x 8
    int ib = blockIdx.x * 32;                  // i tile (32)
    int cb = blockIdx.y * 64;                  // c tile (64)
    #pragma unroll
    for (int j = 0; j < 64; j += 8) {
        int c_loc = ty + j;
        tB[tx][c_loc] = g_Bt[(size_t)(cb + c_loc) * FN + ib + tx];
        tR[tx][c_loc] = g_R [(size_t)(cb + c_loc) * FN + ib + tx];
    }
    __syncthreads();
    float4* o4 = reinterpret_cast<float4*>(out);   // row stride 2048 float4
    int cq = (cb >> 1) + tx;                       // float4 col index
    #pragma unroll
    for (int j = 0; j < 32; j += 8) {
        int i_loc = ty + j;
        size_t ig = (size_t)(ib + i_loc);
        float2 a0 = __half22float2(tB[i_loc][2 * tx]);
        float2 a1 = __half22float2(tB[i_loc][2 * tx + 1]);
        o4[(2 * ig) * 2048 + cq] = make_float4(a0.x, a0.y, a1.x, a1.y);
        float2 b0 = __half22float2(tR[i_loc][2 * tx]);
        float2 b1 = __half22float2(tR[i_loc][2 * tx + 1]);
        o4[(2 * ig + 1) * 2048 + cq] = make_float4(b0.x, b0.y, b1.x, b1.y);
    }
}

extern "C" void kernel_launch(void* const* d_in, const int* in_sizes, int n_in,
                              void* d_out, int out_size) {
    const float* x = (const float*)d_in[0];
    float* out = (float*)d_out;
    (void)in_sizes; (void)n_in; (void)out_size;

    cudaFuncSetAttribute(k1_rowpass, cudaFuncAttributeMaxDynamicSharedMemorySize,
                         (int)SMEM_FFT);
    cudaFuncSetAttribute(k3_colpass, cudaFuncAttributeMaxDynamicSharedMemorySize,
                         (int)SMEM_FFT);

    k0_twiddle<<<1, 512>>>();
    k1_rowpass<<<NPAIR, TPB, SMEM_FFT>>>(x);
    k_reduce<<<1, TPB>>>();
    k2_transpose<<<dim3(FN / 32, FN / 32), dim3(32, 8)>>>();
    k3_colpass<<<FN, TPB, SMEM_FFT>>>();
    k4_assemble<<<dim3(FN / 32, FN / 64), dim3(32, 8)>>>(out);
}

// round 8
// speedup vs baseline: 1.1091x; 1.1091x over previous
#include <cuda_runtime.h>
#include <cuda_fp16.h>
#include <cuda_bf16.h>

// FFT-based 2x upsample, fully-real polyphase formulation (see R2/R3/R5).
// R8 = R5 baseline (best: 228us) +
//   (a) swizzled smem addresses factored into per-thread bases + immediates
//       (SW is GF(2)-linear; all six exchange patterns split over disjoint
//        bit fields — addresses identical to R5, far fewer ALU ops), and
//   (b) K4 with 64-wide tiles + float4 stores.
// R6/R7 occupancy experiments reverted (both regressed: spills / extra LDS).

#define FN    4096
#define TPB   512
#define NPAIR (FN / 2)
#define SMEM_FFT (2 * FN * sizeof(float2))   // 64 KB double-buffer

__device__ __align__(16) __half2 g_B [(size_t)FN * FN];  // (x, R_row)
__device__ __align__(16) __half2 g_Bt[(size_t)FN * FN];  // B transposed
__device__ __align__(16) __half2 g_R [(size_t)FN * FN];  // (Ru, Rv') per (c,i)
__device__ float g_Dpart[NPAIR];
__device__ float g_D[1];
// twA[k] = e^{-2 pi i k/4096}, twB[k] = e^{+i pi k/4096}, k < 512
__device__ __align__(16) float2 g_twA[512];
__device__ __align__(16) float2 g_twB[512];

__device__ __forceinline__ float2 cmul(float2 a, float2 b) {
    return make_float2(fmaf(a.x, b.x, -a.y * b.y), fmaf(a.x, b.y, a.y * b.x));
}
__device__ __forceinline__ float2 cadd(float2 a, float2 b) { return make_float2(a.x + b.x, a.y + b.y); }
__device__ __forceinline__ float2 csub(float2 a, float2 b) { return make_float2(a.x - b.x, a.y - b.y); }
__device__ __forceinline__ float2 cconj(float2 a) { return make_float2(a.x, -a.y); }

__global__ void k0_twiddle() {
    int k = threadIdx.x;
    float sn, cs;
    sincospif(-(float)k / 2048.0f, &sn, &cs);
    g_twA[k] = make_float2(cs, sn);
    sincospif((float)k / 4096.0f, &sn, &cs);
    g_twB[k] = make_float2(cs, sn);
}

// Radix-8 DFT butterfly. FWD: W_8 = e^{-2pi i/8}; INV: conjugate.
template <bool INV>
__device__ __forceinline__ void bfly8(const float2 x[8], float2 y[8]) {
    float2 a0 = cadd(x[0], x[4]), a1 = csub(x[0], x[4]);
    float2 a2 = cadd(x[2], x[6]), a3 = csub(x[2], x[6]);
    float2 a4 = cadd(x[1], x[5]), a5 = csub(x[1], x[5]);
    float2 a6 = cadd(x[3], x[7]), a7 = csub(x[3], x[7]);
    float2 b0 = cadd(a0, a2), b1 = csub(a0, a2);
    float2 b2 = cadd(a4, a6), b3 = csub(a4, a6);
    float2 c3  = INV ? make_float2(-a3.y, a3.x) : make_float2(a3.y, -a3.x);
    float2 c7  = INV ? make_float2(-a7.y, a7.x) : make_float2(a7.y, -a7.x);
    float2 jb3 = INV ? make_float2(-b3.y, b3.x) : make_float2(b3.y, -b3.x);
    float2 e1 = cadd(a1, c3), e3 = csub(a1, c3);
    float2 f5 = cadd(a5, c7), f7 = csub(a5, c7);
    const float s = 0.70710678118654752440f;
    float2 W1 = INV ? make_float2(s, s)  : make_float2(s, -s);
    float2 W3 = INV ? make_float2(-s, s) : make_float2(-s, -s);
    float2 g5 = cmul(W1, f5), g7 = cmul(W3, f7);
    y[0] = cadd(b0, b2); y[4] = csub(b0, b2);
    y[2] = cadd(b1, jb3); y[6] = csub(b1, jb3);
    y[1] = cadd(e1, g5); y[5] = csub(e1, g5);
    y[3] = cadd(e3, g7); y[7] = csub(e3, g7);
}

__device__ __forceinline__ void twapply(float2 y[8], float2 w) {
    float2 wk = w;
    y[1] = cmul(y[1], wk);
    #pragma unroll
    for (int k = 2; k < 8; k++) { wk = cmul(wk, w); y[k] = cmul(y[k], wk); }
}

// S-transform: z <- N * IDFT( DFT(z) * halfshift_w ), zny <- DFT(z)[2048].
// Exchange addresses: same values as R5's SW(.), factored into per-thread
// bases + per-q immediates/consts (SW is GF(2)-linear, fields disjoint):
//  P1: SW(512q+tid)            = swtid + 512q
//  P2: SW(512k0+64q+s6)        = (q odd ? b2x : b2) + 64q
//  P3: SW(512k0+64k1+8q+n0)    = (b3a + 8q) ^ M[q>>1],  M = m9 ^ {0,4,2,6}
//  P4: SW(8tid+q)              = b4 ^ q
__device__ __forceinline__ void stransform(float2 z[8], float2* buf0, float2* buf1,
                                           float2* s_zny, int tid, float2* zny_out) {
    const int k0 = tid >> 6;
    const int s6 = tid & 63;
    const int k1 = (tid >> 3) & 7;
    const int n0 = tid & 7;
    const int m  = k0 + 8 * k1 + 64 * n0;

    const int swtid = tid ^ ((tid >> 2) & 4) ^ ((tid >> 4) & 2) ^ (((tid >> 6) & 1) * 9);
    const int b2    = 512 * k0 + (s6 ^ ((s6 >> 2) & 4) ^ ((s6 >> 4) & 2));
    const int b2x   = b2 ^ 9;
    const int b3a   = 512 * k0 + 64 * k1 + n0;
    const int m9    = (k1 & 1) * 9;
    const int M0 = m9, M1 = m9 ^ 4, M2 = m9 ^ 2, M3 = m9 ^ 6;
    const int b4    = (8 * tid) ^ (((tid & 2) << 1) ^ ((tid & 4) >> 1) ^ ((tid & 8) ? 9 : 0));

    float2 y[8], t[8];

    const float2 w1b = __ldg(&g_twA[tid]);
    const float2 w2b = __ldg(&g_twA[8 * s6]);
    const float2 w3b = __ldg(&g_twA[64 * n0]);
    const float2 wm  = __ldg(&g_twB[m]);

    // ---- forward FFT ----
    bfly8<false>(z, y);
    twapply(y, w1b);
    #pragma unroll
    for (int q = 0; q < 8; q++) buf0[swtid + 512 * q] = y[q];
    __syncthreads();
    #pragma unroll
    for (int q = 0; q < 8; q++) t[q] = buf0[((q & 1) ? b2x : b2) + 64 * q];

    bfly8<false>(t, y);
    twapply(y, w2b);
    #pragma unroll
    for (int q = 0; q < 8; q++) buf1[((q & 1) ? b2x : b2) + 64 * q] = y[q];
    __syncthreads();
    {
        t[0] = buf1[(b3a +  0) ^ M0]; t[1] = buf1[(b3a +  8) ^ M0];
        t[2] = buf1[(b3a + 16) ^ M1]; t[3] = buf1[(b3a + 24) ^ M1];
        t[4] = buf1[(b3a + 32) ^ M2]; t[5] = buf1[(b3a + 40) ^ M2];
        t[6] = buf1[(b3a + 48) ^ M3]; t[7] = buf1[(b3a + 56) ^ M3];
    }

    bfly8<false>(t, y);
    twapply(y, w3b);
    {
        buf0[(b3a +  0) ^ M0] = y[0]; buf0[(b3a +  8) ^ M0] = y[1];
        buf0[(b3a + 16) ^ M1] = y[2]; buf0[(b3a + 24) ^ M1] = y[3];
        buf0[(b3a + 32) ^ M2] = y[4]; buf0[(b3a + 40) ^ M2] = y[5];
        buf0[(b3a + 48) ^ M3] = y[6]; buf0[(b3a + 56) ^ M3] = y[7];
    }
    __syncthreads();
    #pragma unroll
    for (int q = 0; q < 8; q++) t[q] = buf0[b4 ^ q];

    bfly8<false>(t, y);                         // -> X[m + 512 j]
    if (tid == 0) *s_zny = y[4];                // zny = X[2048]

    // ---- half-sample-shift phase (registers) ----
    {
        const float2 EJ[8] = {
            { 1.0f, 0.0f},
            { 0.92387953251128675613f,  0.38268343236508977173f},
            { 0.70710678118654752440f,  0.70710678118654752440f},
            { 0.38268343236508977173f,  0.92387953251128675613f},
            { 0.0f, -1.0f},
            { 0.38268343236508977173f, -0.92387953251128675613f},
            { 0.70710678118654752440f, -0.70710678118654752440f},
            { 0.92387953251128675613f, -0.38268343236508977173f}};
        #pragma unroll
        for (int j = 0; j < 8; j++) y[j] = cmul(y[j], cmul(wm, EJ[j]));
    }

    // ---- inverse FFT ----
    bfly8<true>(y, t);
    #pragma unroll
    for (int q = 0; q < 8; q++) buf1[b4 ^ q] = t[q];
    __syncthreads();
    {
        t[0] = buf1[(b3a +  0) ^ M0]; t[1] = buf1[(b3a +  8) ^ M0];
        t[2] = buf1[(b3a + 16) ^ M1]; t[3] = buf1[(b3a + 24) ^ M1];
        t[4] = buf1[(b3a + 32) ^ M2]; t[5] = buf1[(b3a + 40) ^ M2];
        t[6] = buf1[(b3a + 48) ^ M3]; t[7] = buf1[(b3a + 56) ^ M3];
    }

    twapply(t, cconj(w3b));
    bfly8<true>(t, y);
    {
        buf0[(b3a +  0) ^ M0] = y[0]; buf0[(b3a +  8) ^ M0] = y[1];
        buf0[(b3a + 16) ^ M1] = y[2]; buf0[(b3a + 24) ^ M1] = y[3];
        buf0[(b3a + 32) ^ M2] = y[4]; buf0[(b3a + 40) ^ M2] = y[5];
        buf0[(b3a + 48) ^ M3] = y[6]; buf0[(b3a + 56) ^ M3] = y[7];
    }
    __syncthreads();
    #pragma unroll
    for (int q = 0; q < 8; q++) t[q] = buf0[((q & 1) ? b2x : b2) + 64 * q];

    twapply(t, cconj(w2b));
    bfly8<true>(t, y);
    #pragma unroll
    for (int q = 0; q < 8; q++) buf1[((q & 1) ? b2x : b2) + 64 * q] = y[q];
    __syncthreads();
    #pragma unroll
    for (int q = 0; q < 8; q++) t[q] = buf1[swtid + 512 * q];

    twapply(t, cconj(w1b));
    bfly8<true>(t, z);                          // z[n3] = N*S[tid+512 n3]

    *zny_out = *s_zny;                          // >= 3 syncs after the write
}

// K1: 2-for-1 row pass (block r handles input rows 2r, 2r+1).
__global__ __launch_bounds__(TPB) void k1_rowpass(const float* __restrict__ x) {
    extern __shared__ float2 dsm[];
    __shared__ float2 s_zny;
    float2* buf0 = dsm;
    float2* buf1 = dsm + FN;
    int tid = threadIdx.x;
    size_t r = blockIdx.x;
    const float* u = x + (2 * r) * (size_t)FN;
    const float* v = u + FN;
    float2 z[8], z0[8];
    #pragma unroll
    for (int e = 0; e < 8; e++) {
        int j = tid + e * TPB;
        z[e] = make_float2(u[j], v[j]);
        z0[e] = z[e];
    }
    float2 zny;
    stransform(z, buf0, buf1, &s_zny, tid, &zny);
    if (tid == 0) g_Dpart[r] = zny.x - zny.y;

    const float invN = 1.0f / 4096.0f;
    float sgn = (tid & 1) ? -1.0f : 1.0f;       // (-1)^j
    __half2* row0 = g_B + (2 * r) * (size_t)FN;
    __half2* row1 = row0 + FN;
    #pragma unroll
    for (int e = 0; e < 8; e++) {
        int j = tid + e * TPB;
        float Ru = (z[e].x - sgn * zny.y) * invN;
        float Rv = (z[e].y + sgn * zny.x) * invN;
        row0[j] = __floats2half2_rn(z0[e].x, Ru);
        row1[j] = __floats2half2_rn(z0[e].y, Rv);
    }
}

// Deterministic reduction of g_Dpart -> g_D.
__global__ void k_reduce() {
    __shared__ float sh[TPB];
    float s = 0.0f;
    for (int i = threadIdx.x; i < NPAIR; i += TPB) s += g_Dpart[i];
    sh[threadIdx.x] = s;
    __syncthreads();
    for (int o = TPB / 2; o > 0; o >>= 1) {
        if (threadIdx.x < o) sh[threadIdx.x] += sh[threadIdx.x + o];
        __syncthreads();
    }
    if (threadIdx.x == 0) g_D[0] = sh[0];
}

// K2: transpose B [4096x4096 half2] -> Bt.
__global__ void k2_transpose() {
    __shared__ __half2 tile[32][33];
    int tx = threadIdx.x, ty = threadIdx.y;
    int cx = blockIdx.x * 32 + tx;
    int ry = blockIdx.y * 32 + ty;
    #pragma unroll
    for (int j = 0; j < 32; j += 8)
        tile[ty + j][tx] = g_B[(size_t)(ry + j) * FN + cx];
    __syncthreads();
    int ox = blockIdx.y * 32 + tx;
    int oy = blockIdx.x * 32 + ty;
    #pragma unroll
    for (int j = 0; j < 32; j += 8)
        g_Bt[(size_t)(oy + j) * FN + ox] = tile[tx][ty + j];
}

// K3: 2-for-1 column pass (block c handles output columns 2c, 2c+1).
// Writes ONLY the odd-row values: R[c][i] = (Ru, Rv + parity corr).
__global__ __launch_bounds__(TPB) void k3_colpass() {
    extern __shared__ float2 dsm[];
    __shared__ float2 s_zny;
    float2* buf0 = dsm;
    float2* buf1 = dsm + FN;
    int tid = threadIdx.x;
    size_t c = blockIdx.x;
    const __half2* bt = g_Bt + c * (size_t)FN;
    float2 z[8];
    #pragma unroll
    for (int e = 0; e < 8; e++) {
        int j = tid + e * TPB;
        z[e] = __half22float2(bt[j]);
    }
    float2 zny;
    stransform(z, buf0, buf1, &s_zny, tid, &zny);

    const float invN = 1.0f / 4096.0f;
    float corr = -g_D[0] * invN * invN;         // -D/N^2
    float sgnc = (c & 1) ? -corr : corr;        // (-1)^c * corr
    float sgn = (tid & 1) ? -1.0f : 1.0f;       // (-1)^i
    __half2* rr = g_R + c * (size_t)FN;
    #pragma unroll
    for (int e = 0; e < 8; e++) {
        int j = tid + e * TPB;
        float Ru = (z[e].x - sgn * zny.y) * invN;
        float Rv = (z[e].y + sgn * zny.x) * invN;
        rr[j] = __floats2half2_rn(Ru, Rv + sgn * sgnc);
    }
}

// K4: assemble output from Bt + R; 64-wide c tiles, float4 stores.
//   out[2i  ][2c..2c+1] = Bt[c][i]   out[2i+1][2c..2c+1] = R[c][i]
__global__ void k4_assemble(float* __restrict__ out) {
    __shared__ __half2 tB[32][66];   // [i_loc][c_loc], +2 pad
    __shared__ __half2 tR[32][66];
    int tx = threadIdx.x, ty = threadIdx.y;    // 32 x 8
    int ib = blockIdx.x * 32;                  // i tile (32)
    int cb = blockIdx.y * 64;                  // c tile (64)
    #pragma unroll
    for (int j = 0; j < 64; j += 8) {
        int c_loc = ty + j;
        tB[tx][c_loc] = g_Bt[(size_t)(cb + c_loc) * FN + ib + tx];
        tR[tx][c_loc] = g_R [(size_t)(cb + c_loc) * FN + ib + tx];
    }
    __syncthreads();
    float4* o4 = reinterpret_cast<float4*>(out);   // row stride 2048 float4
    int cq = (cb >> 1) + tx;                       // float4 col index
    #pragma unroll
    for (int j = 0; j < 32; j += 8) {
        int i_loc = ty + j;
        size_t ig = (size_t)(ib + i_loc);
        float2 a0 = __half22float2(tB[i_loc][2 * tx]);
        float2 a1 = __half22float2(tB[i_loc][2 * tx + 1]);
        o4[(2 * ig) * 2048 + cq] = make_float4(a0.x, a0.y, a1.x, a1.y);
        float2 b0 = __half22float2(tR[i_loc][2 * tx]);
        float2 b1 = __half22float2(tR[i_loc][2 * tx + 1]);
        o4[(2 * ig + 1) * 2048 + cq] = make_float4(b0.x, b0.y, b1.x, b1.y);
    }
}

extern "C" void kernel_launch(void* const* d_in, const int* in_sizes, int n_in,
                              void* d_out, int out_size) {
    const float* x = (const float*)d_in[0];
    float* out = (float*)d_out;
    (void)in_sizes; (void)n_in; (void)out_size;

    cudaFuncSetAttribute(k1_rowpass, cudaFuncAttributeMaxDynamicSharedMemorySize,
                         (int)SMEM_FFT);
    cudaFuncSetAttribute(k3_colpass, cudaFuncAttributeMaxDynamicSharedMemorySize,
                         (int)SMEM_FFT);

    k0_twiddle<<<1, 512>>>();
    k1_rowpass<<<NPAIR, TPB, SMEM_FFT>>>(x);
    k_reduce<<<1, TPB>>>();
    k2_transpose<<<dim3(FN / 32, FN / 32), dim3(32, 8)>>>();
    k3_colpass<<<FN, TPB, SMEM_FFT>>>();
    k4_assemble<<<dim3(FN / 32, FN / 64), dim3(32, 8)>>>(out);
}